// round 1
// baseline (speedup 1.0000x reference)
#include <cuda_runtime.h>
#include <cuda_bf16.h>

#define NN      4096
#define NIN     64
#define NHID    32
#define NOUT    64
#define NHEADS  8
#define H_SP    6
#define D_INT   32
#define CAP     256      // max neighbors per row (binomial(4096,0.01) max ~70 + self loop)
#define ALPHA   0.2f

// ---------------- scratch (no allocations allowed) ----------------
__device__ int   g_deg[NN];
__device__ int   g_nbr[NN * CAP];
__device__ float g_Wh[NHEADS * NN * NHID];   // [h][n][32]
__device__ float g_f1[NHEADS * NN];
__device__ float g_f2[NHEADS * NN];
__device__ float g_h[NN * (NHEADS * NHID)];  // [n][256] concat
__device__ float g_Who[NN * NOUT];
__device__ float g_o1[NN];
__device__ float g_o2[NN];

__device__ __forceinline__ float warp_max(float v) {
    #pragma unroll
    for (int o = 16; o; o >>= 1) v = fmaxf(v, __shfl_xor_sync(0xffffffffu, v, o));
    return v;
}
__device__ __forceinline__ float warp_sum(float v) {
    #pragma unroll
    for (int o = 16; o; o >>= 1) v += __shfl_xor_sync(0xffffffffu, v, o);
    return v;
}
__device__ __forceinline__ float lrelu(float s) { return s > 0.f ? s : ALPHA * s; }

// ---------------- 1: build neighbor lists (one warp per row) ----------------
__global__ void k_build(const float* __restrict__ adj) {
    int row  = blockIdx.x * (blockDim.x >> 5) + (threadIdx.x >> 5);
    int lane = threadIdx.x & 31;
    if (row >= NN) return;
    const float4* r = reinterpret_cast<const float4*>(adj + (size_t)row * NN);
    int count = 0;
    int* nb = g_nbr + row * CAP;
    unsigned lmask = (1u << lane) - 1u;
    for (int base = 0; base < NN; base += 128) {
        float4 v = r[(base >> 2) + lane];
        float vals[4] = {v.x, v.y, v.z, v.w};
        #pragma unroll
        for (int e = 0; e < 4; e++) {
            bool p = vals[e] > 0.f;
            unsigned m = __ballot_sync(0xffffffffu, p);
            int pos = count + __popc(m & lmask);
            if (p && pos < CAP) nb[pos] = base + lane * 4 + e;
            count += __popc(m);
        }
    }
    if (lane == 0) g_deg[row] = count < CAP ? count : CAP;
}

// ---------------- 2: projections + attention scalars ----------------
// grid (NN/8, NHEADS), block (32, 8): warp = one row, lane = out-dim
__global__ void k_proj(const float* __restrict__ x,
                       const float* __restrict__ ie,
                       const float* __restrict__ W_sp, const float* __restrict__ a_sp,
                       const float* __restrict__ W_int, const float* __restrict__ a_int) {
    int h    = blockIdx.y;
    int r0   = blockIdx.x * 8;
    int lane = threadIdx.x;
    int rr   = threadIdx.y;
    int tid  = rr * 32 + lane;
    __shared__ float sW[NIN * NHID];   // 8KB
    __shared__ float sx[8 * NIN];      // 2KB
    __shared__ float sa[64];
    const float* W = (h < H_SP) ? (W_sp + (size_t)h * NIN * NHID)
                                : (W_int + (size_t)(h - H_SP) * NIN * NHID);
    for (int i = tid; i < NIN * NHID; i += 256) sW[i] = W[i];
    for (int i = tid; i < 8 * NIN;    i += 256) sx[i] = x[(size_t)r0 * NIN + i];
    if (tid < 64) sa[tid] = (h < H_SP) ? a_sp[h * 64 + tid] : a_int[(h - H_SP) * 64 + tid];
    __syncthreads();

    int row = r0 + rr;
    float acc = 0.f;
    #pragma unroll
    for (int k = 0; k < NIN; k++) acc = fmaf(sx[rr * NIN + k], sW[k * NHID + lane], acc);
    g_Wh[((size_t)h * NN + row) * NHID + lane] = acc;

    float p1, p2;
    if (h < H_SP) {
        p1 = acc * sa[lane];
        p2 = acc * sa[32 + lane];
    } else {
        float iv = ie[(size_t)row * D_INT + lane];
        p1 = iv * sa[lane];
        p2 = iv * sa[32 + lane];
    }
    p1 = warp_sum(p1);
    p2 = warp_sum(p2);
    if (lane == 0) { g_f1[h * NN + row] = p1; g_f2[h * NN + row] = p2; }
}

// ---------------- 3: sparse masked softmax + aggregate + elu ----------------
// grid NN, block 256: warp h handles (row, head h); lane = feature dim
__global__ void k_att() {
    int row  = blockIdx.x;
    int h    = threadIdx.x >> 5;
    int lane = threadIdx.x & 31;
    int deg  = g_deg[row];
    const int* nb = g_nbr + row * CAP;
    const float* f2 = g_f2 + h * NN;
    float fi = g_f1[h * NN + row];

    float mx = -1e30f;
    for (int t = lane; t < deg; t += 32) {
        float s = lrelu(fi + f2[nb[t]]);
        mx = fmaxf(mx, s);
    }
    mx = warp_max(mx);
    float sm = 0.f;
    for (int t = lane; t < deg; t += 32) {
        float s = lrelu(fi + f2[nb[t]]);
        sm += __expf(s - mx);
    }
    sm = warp_sum(sm);
    float inv = 1.f / sm;

    const float* Wh = g_Wh + (size_t)h * NN * NHID;
    float acc = 0.f;
    for (int t = 0; t < deg; t++) {
        int j = nb[t];
        float s = lrelu(fi + f2[j]);           // broadcast (same addr all lanes)
        float w = __expf(s - mx) * inv;
        acc = fmaf(w, Wh[(size_t)j * NHID + lane], acc);
    }
    // elu (concat=True path)
    acc = acc > 0.f ? acc : (__expf(acc) - 1.f);
    g_h[(size_t)row * (NHEADS * NHID) + h * NHID + lane] = acc;
}

// ---------------- 4: Who = h @ W_out ----------------
// grid NN/4, block 256 (4 rows x 64 cols)
__global__ void k_who(const float* __restrict__ W_out) {
    int r0 = blockIdx.x * 4;
    int c  = threadIdx.x & 63;
    int rr = threadIdx.x >> 6;
    __shared__ float sh[4 * 256];   // 4KB
    for (int i = threadIdx.x; i < 4 * 256; i += 256)
        sh[i] = g_h[(size_t)r0 * 256 + i];
    __syncthreads();
    float acc = 0.f;
    #pragma unroll 4
    for (int k = 0; k < 256; k++)
        acc = fmaf(sh[rr * 256 + k], __ldg(&W_out[k * 64 + c]), acc);
    g_Who[(size_t)(r0 + rr) * NOUT + c] = acc;
}

// ---------------- 5: o1/o2 dots (one warp per row) ----------------
__global__ void k_o12(const float* __restrict__ a_out) {
    int row  = blockIdx.x * 8 + (threadIdx.x >> 5);
    int lane = threadIdx.x & 31;
    float v0 = g_Who[(size_t)row * 64 + lane];
    float v1 = g_Who[(size_t)row * 64 + 32 + lane];
    float p1 = v0 * a_out[lane] + v1 * a_out[32 + lane];
    float p2 = v0 * a_out[64 + lane] + v1 * a_out[96 + lane];
    p1 = warp_sum(p1);
    p2 = warp_sum(p2);
    if (lane == 0) { g_o1[row] = p1; g_o2[row] = p2; }
}

// ---------------- 6: output attention + tanh ----------------
// grid NN/4, block 256: warp w -> row r0 + w/2, half (w&1); each warp computes
// full softmax stats redundantly (strided over all neighbors), no smem needed.
__global__ void k_out(float* __restrict__ out) {
    int w    = threadIdx.x >> 5;
    int lane = threadIdx.x & 31;
    int row  = blockIdx.x * 4 + (w >> 1);
    int d    = (w & 1) * 32 + lane;
    int deg  = g_deg[row];
    const int* nb = g_nbr + row * CAP;
    float oi = g_o1[row];

    float mx = -1e30f;
    for (int t = lane; t < deg; t += 32) {
        float s = lrelu(oi + g_o2[nb[t]]);
        mx = fmaxf(mx, s);
    }
    mx = warp_max(mx);
    float sm = 0.f;
    for (int t = lane; t < deg; t += 32) {
        float s = lrelu(oi + g_o2[nb[t]]);
        sm += __expf(s - mx);
    }
    sm = warp_sum(sm);
    float inv = 1.f / sm;

    float acc = 0.f;
    for (int t = 0; t < deg; t++) {
        int j = nb[t];
        float s = lrelu(oi + g_o2[j]);
        acc = fmaf(__expf(s - mx) * inv, g_Who[(size_t)j * 64 + d], acc);
    }
    out[(size_t)row * NOUT + d] = tanhf(acc);
}

// ---------------- launch ----------------
extern "C" void kernel_launch(void* const* d_in, const int* in_sizes, int n_in,
                              void* d_out, int out_size) {
    const float* x     = (const float*)d_in[0];
    const float* adj   = (const float*)d_in[1];
    const float* ie    = (const float*)d_in[2];
    const float* W_sp  = (const float*)d_in[3];
    const float* a_sp  = (const float*)d_in[4];
    const float* W_int = (const float*)d_in[5];
    const float* a_int = (const float*)d_in[6];
    const float* W_out = (const float*)d_in[7];
    const float* a_out = (const float*)d_in[8];
    float* out = (float*)d_out;

    k_build<<<NN / 8, 256>>>(adj);
    k_proj<<<dim3(NN / 8, NHEADS), dim3(32, 8)>>>(x, ie, W_sp, a_sp, W_int, a_int);
    k_att<<<NN, 256>>>();
    k_who<<<NN / 4, 256>>>(W_out);
    k_o12<<<NN / 8, 256>>>(a_out);
    k_out<<<NN / 4, 256>>>(out);
}

// round 5
// speedup vs baseline: 1.2096x; 1.2096x over previous
#include <cuda_runtime.h>
#include <cuda_bf16.h>

#define NN      4096
#define NIN     64
#define NHID    32
#define NOUT    64
#define NHEADS  8
#define H_SP    6
#define D_INT   32
#define CAP     256
#define ALPHA   0.2f

// ---------------- scratch ----------------
__device__ int   g_deg[NN];
__device__ int   g_nbr[NN * CAP];
__device__ float g_Wh[NHEADS * NN * NHID];   // [h][n][32]
__device__ float g_f1[NHEADS * NN];          // [h][n]
__device__ float g_f2p[NN * NHEADS];         // [n][8]  packed for 32B edge loads
__device__ float g_h[NN * (NHEADS * NHID)];  // [n][256]
__device__ float g_Who[NN * NOUT];           // [n][64]
__device__ float g_o1[NN];
__device__ float g_o2[NN];

__device__ __forceinline__ float warp_max(float v) {
    #pragma unroll
    for (int o = 16; o; o >>= 1) v = fmaxf(v, __shfl_xor_sync(0xffffffffu, v, o));
    return v;
}
__device__ __forceinline__ float warp_sum(float v) {
    #pragma unroll
    for (int o = 16; o; o >>= 1) v += __shfl_xor_sync(0xffffffffu, v, o);
    return v;
}
__device__ __forceinline__ float lrelu(float s) { return s > 0.f ? s : ALPHA * s; }

// ---------------- 1: neighbor lists (warp/row, MLP=4) ----------------
__global__ void k_build(const float* __restrict__ adj) {
    int row  = blockIdx.x * (blockDim.x >> 5) + (threadIdx.x >> 5);
    int lane = threadIdx.x & 31;
    const float4* r = reinterpret_cast<const float4*>(adj + (size_t)row * NN);
    int count = 0;
    int* nb = g_nbr + row * CAP;
    unsigned lmask = (1u << lane) - 1u;
    #pragma unroll 1
    for (int it = 0; it < 8; it++) {
        float4 v[4];
        #pragma unroll
        for (int q = 0; q < 4; q++) v[q] = r[it * 128 + q * 32 + lane];   // 4 loads in flight
        #pragma unroll
        for (int q = 0; q < 4; q++) {
            int base = it * 512 + q * 128 + lane * 4;
            float vals[4] = {v[q].x, v[q].y, v[q].z, v[q].w};
            #pragma unroll
            for (int e = 0; e < 4; e++) {
                bool p = vals[e] > 0.f;
                unsigned m = __ballot_sync(0xffffffffu, p);
                int pos = count + __popc(m & lmask);
                if (p && pos < CAP) nb[pos] = base + e;
                count += __popc(m);
            }
        }
    }
    if (lane == 0) g_deg[row] = count < CAP ? count : CAP;
}

// ---------------- 2: projections + attention scalars ----------------
__global__ void k_proj(const float* __restrict__ x,
                       const float* __restrict__ ie,
                       const float* __restrict__ W_sp, const float* __restrict__ a_sp,
                       const float* __restrict__ W_int, const float* __restrict__ a_int) {
    int h    = blockIdx.y;
    int r0   = blockIdx.x * 8;
    int lane = threadIdx.x;
    int rr   = threadIdx.y;
    int tid  = rr * 32 + lane;
    __shared__ float sW[NIN * NHID];
    __shared__ float sx[8 * NIN];
    __shared__ float sa[64];
    const float* W = (h < H_SP) ? (W_sp + (size_t)h * NIN * NHID)
                                : (W_int + (size_t)(h - H_SP) * NIN * NHID);
    for (int i = tid; i < NIN * NHID; i += 256) sW[i] = W[i];
    for (int i = tid; i < 8 * NIN;    i += 256) sx[i] = x[(size_t)r0 * NIN + i];
    if (tid < 64) sa[tid] = (h < H_SP) ? a_sp[h * 64 + tid] : a_int[(h - H_SP) * 64 + tid];
    __syncthreads();

    int row = r0 + rr;
    float acc = 0.f;
    #pragma unroll
    for (int k = 0; k < NIN; k++) acc = fmaf(sx[rr * NIN + k], sW[k * NHID + lane], acc);
    g_Wh[((size_t)h * NN + row) * NHID + lane] = acc;

    float p1, p2;
    if (h < H_SP) {
        p1 = acc * sa[lane];
        p2 = acc * sa[32 + lane];
    } else {
        float iv = ie[(size_t)row * D_INT + lane];
        p1 = iv * sa[lane];
        p2 = iv * sa[32 + lane];
    }
    p1 = warp_sum(p1);
    p2 = warp_sum(p2);
    if (lane == 0) { g_f1[h * NN + row] = p1; g_f2p[row * NHEADS + h] = p2; }
}

// ---------------- 3: sparse softmax + aggregate + elu (block/row) ----------------
__global__ void k_att() {
    __shared__ int   snb[CAP];
    __shared__ float sw[NHEADS][CAP];
    __shared__ float sf1[NHEADS];
    int row = blockIdx.x;
    int tid = threadIdx.x;
    int deg = g_deg[row];
    if (tid < NHEADS) sf1[tid] = g_f1[tid * NN + row];
    for (int t = tid; t < deg; t += 256) snb[t] = g_nbr[row * CAP + t];
    __syncthreads();
    for (int t = tid; t < deg; t += 256) {
        int j = snb[t];
        float4 a = *reinterpret_cast<const float4*>(&g_f2p[(size_t)j * 8]);
        float4 b = *reinterpret_cast<const float4*>(&g_f2p[(size_t)j * 8 + 4]);
        sw[0][t] = lrelu(sf1[0] + a.x);  sw[1][t] = lrelu(sf1[1] + a.y);
        sw[2][t] = lrelu(sf1[2] + a.z);  sw[3][t] = lrelu(sf1[3] + a.w);
        sw[4][t] = lrelu(sf1[4] + b.x);  sw[5][t] = lrelu(sf1[5] + b.y);
        sw[6][t] = lrelu(sf1[6] + b.z);  sw[7][t] = lrelu(sf1[7] + b.w);
    }
    __syncthreads();

    int h = tid >> 5, lane = tid & 31;
    float mx = -1e30f;
    for (int t = lane; t < deg; t += 32) mx = fmaxf(mx, sw[h][t]);
    mx = warp_max(mx);
    float sm = 0.f;
    for (int t = lane; t < deg; t += 32) {
        float e = __expf(sw[h][t] - mx);
        sw[h][t] = e;                       // store weight once
        sm += e;
    }
    sm = warp_sum(sm);
    __syncwarp();
    float inv = 1.f / sm;

    const float* Wh = g_Wh + (size_t)h * NN * NHID;
    float acc = 0.f;
    for (int t = 0; t < deg; t++) {
        int j = snb[t];
        acc = fmaf(sw[h][t] * inv, Wh[(size_t)j * NHID + lane], acc);
    }
    acc = acc > 0.f ? acc : (__expf(acc) - 1.f);
    g_h[(size_t)row * 256 + h * NHID + lane] = acc;
}

// ---------------- 4: Who = h @ W_out, fused o1/o2 ----------------
#define WHO_ROWS 16
__global__ void k_who(const float* __restrict__ W_out, const float* __restrict__ a_out) {
    int r0   = blockIdx.x * WHO_ROWS;
    int tid  = threadIdx.x;
    int c    = tid & 63;
    int rg   = tid >> 6;          // 0..3 -> rows rg*4 .. rg*4+3
    int w    = tid >> 5;          // warp 0..7
    int lane = tid & 31;
    __shared__ float sh[WHO_ROWS][256];   // 16KB
    __shared__ float sp1[8][4], sp2[8][4];
    for (int i = tid; i < WHO_ROWS * 256; i += 256)
        sh[i >> 8][i & 255] = g_h[(size_t)r0 * 256 + i];
    __syncthreads();

    float acc[4] = {0.f, 0.f, 0.f, 0.f};
    #pragma unroll 4
    for (int k = 0; k < 256; k++) {
        float wv = __ldg(&W_out[k * 64 + c]);
        #pragma unroll
        for (int i = 0; i < 4; i++)
            acc[i] = fmaf(sh[rg * 4 + i][k], wv, acc[i]);
    }
    float a1 = __ldg(&a_out[c]), a2 = __ldg(&a_out[64 + c]);
    #pragma unroll
    for (int i = 0; i < 4; i++) {
        g_Who[(size_t)(r0 + rg * 4 + i) * 64 + c] = acc[i];
        float p1 = warp_sum(acc[i] * a1);
        float p2 = warp_sum(acc[i] * a2);
        if (lane == 0) { sp1[w][i] = p1; sp2[w][i] = p2; }
    }
    __syncthreads();
    if (tid < WHO_ROWS) {
        int rgf = tid >> 2, i = tid & 3;
        g_o1[r0 + tid] = sp1[rgf * 2][i] + sp1[rgf * 2 + 1][i];
        g_o2[r0 + tid] = sp2[rgf * 2][i] + sp2[rgf * 2 + 1][i];
    }
}

// ---------------- 5: output attention + tanh (block/row) ----------------
__global__ void k_out(float* __restrict__ out) {
    __shared__ int   snb[CAP];
    __shared__ float sw[CAP];
    __shared__ float sred[8];
    __shared__ float sp[4][64];
    int row = blockIdx.x;
    int tid = threadIdx.x;
    int deg = g_deg[row];
    for (int t = tid; t < deg; t += 256) snb[t] = g_nbr[row * CAP + t];
    __syncthreads();
    float o1r = g_o1[row];
    float lm = -1e30f;
    for (int t = tid; t < deg; t += 256) {
        float s = lrelu(o1r + g_o2[snb[t]]);
        sw[t] = s;
        lm = fmaxf(lm, s);
    }
    lm = warp_max(lm);
    if ((tid & 31) == 0) sred[tid >> 5] = lm;
    __syncthreads();
    float mx = fmaxf(fmaxf(fmaxf(sred[0], sred[1]), fmaxf(sred[2], sred[3])),
                     fmaxf(fmaxf(sred[4], sred[5]), fmaxf(sred[6], sred[7])));
    __syncthreads();
    float ls = 0.f;
    for (int t = tid; t < deg; t += 256) {
        float e = __expf(sw[t] - mx);
        sw[t] = e;
        ls += e;
    }
    ls = warp_sum(ls);
    if ((tid & 31) == 0) sred[tid >> 5] = ls;
    __syncthreads();
    float inv = 1.f / (sred[0] + sred[1] + sred[2] + sred[3] +
                       sred[4] + sred[5] + sred[6] + sred[7]);

    int w = tid >> 5, lane = tid & 31;
    int chunk = w >> 1;             // 0..3
    int d = (w & 1) * 32 + lane;    // 0..63
    float acc = 0.f;
    for (int t = chunk; t < deg; t += 4)
        acc = fmaf(sw[t] * inv, g_Who[(size_t)snb[t] * 64 + d], acc);
    sp[chunk][d] = acc;
    __syncthreads();
    if (tid < 64)
        out[(size_t)row * 64 + tid] =
            tanhf(sp[0][tid] + sp[1][tid] + sp[2][tid] + sp[3][tid]);
}

// ---------------- launch ----------------
extern "C" void kernel_launch(void* const* d_in, const int* in_sizes, int n_in,
                              void* d_out, int out_size) {
    const float* x     = (const float*)d_in[0];
    const float* adj   = (const float*)d_in[1];
    const float* ie    = (const float*)d_in[2];
    const float* W_sp  = (const float*)d_in[3];
    const float* a_sp  = (const float*)d_in[4];
    const float* W_int = (const float*)d_in[5];
    const float* a_int = (const float*)d_in[6];
    const float* W_out = (const float*)d_in[7];
    const float* a_out = (const float*)d_in[8];
    float* out = (float*)d_out;

    k_build<<<NN / 8, 256>>>(adj);
    k_proj<<<dim3(NN / 8, NHEADS), dim3(32, 8)>>>(x, ie, W_sp, a_sp, W_int, a_int);
    k_att<<<NN, 256>>>();
    k_who<<<NN / WHO_ROWS, 256>>>(W_out, a_out);
    k_out<<<NN, 256>>>(out);
}